// round 1
// baseline (speedup 1.0000x reference)
#include <cuda_runtime.h>
#include <cstdint>

#define Dd 2048      // hidden dim
#define Ee 64        // experts
#define TBt 128      // tokens per block
#define BKk 32       // K chunk
#define NTHREADS 256

// Duplicated weight, k-major: g_wdup[k][2e] = g_wdup[k][2e+1] = W[e][k]
__device__ float g_wdup[Dd * 2 * Ee];

__global__ void dup_weight_kernel(const float* __restrict__ w) {
    int i = blockIdx.x * blockDim.x + threadIdx.x;  // i = k*64 + e
    if (i < Dd * Ee) {
        int k = i >> 6;
        int e = i & 63;
        float v = w[e * Dd + k];
        g_wdup[k * 128 + 2 * e]     = v;
        g_wdup[k * 128 + 2 * e + 1] = v;
    }
}

__device__ __forceinline__ void fma2(unsigned long long& d,
                                     unsigned long long a,
                                     unsigned long long b) {
    asm("fma.rn.f32x2 %0, %1, %2, %0;" : "+l"(d) : "l"(a), "l"(b));
}

__device__ __forceinline__ void unpk(unsigned long long v, float& lo, float& hi) {
    asm("mov.b64 {%0, %1}, %2;" : "=f"(lo), "=f"(hi) : "l"(v));
}

__global__ void __launch_bounds__(NTHREADS, 3)
router_kernel(const float* __restrict__ x, float* __restrict__ out, int N) {
    // Union: GEMM staging (Xs + Ws = 8448 floats) reused as logits L (8320 floats)
    __shared__ __align__(16) float smem[2 * BKk * 132];

    float (*Xs)[132] = reinterpret_cast<float(*)[132]>(smem);             // [k][token]
    float (*Ws)[132] = reinterpret_cast<float(*)[132]>(smem + BKk * 132); // [k][2e dup]
    float (*L)[65]   = reinterpret_cast<float(*)[65]>(smem);              // [token][expert]

    const int tid = threadIdx.x;
    const int tx = tid & 15;      // expert tile: experts 4tx..4tx+3
    const int ty = tid >> 4;      // token tile: tokens 8ty..8ty+7
    const long t0 = (long)blockIdx.x * TBt;

    unsigned long long acc[4][4]; // [token-pair][expert], f32x2 packed
    #pragma unroll
    for (int p = 0; p < 4; ++p)
        #pragma unroll
        for (int j = 0; j < 4; ++j) acc[p][j] = 0ull;

    // X loader mapping: 4 passes, each thread one float4
    const int lt = tid >> 3;           // token 0..31 within pass
    const int lk = (tid & 7) * 4;      // k offset (float4)
    const float* xbase = x + (t0 + lt) * (long)Dd + lk;

    for (int kc = 0; kc < Dd / BKk; ++kc) {
        // --- stage X chunk [BKk][TBt], transposed to k-major ---
        #pragma unroll
        for (int pass = 0; pass < 4; ++pass) {
            int t = lt + pass * 32;
            float4 v = *reinterpret_cast<const float4*>(
                xbase + (long)pass * 32 * Dd + (long)kc * BKk);
            Xs[lk + 0][t] = v.x;
            Xs[lk + 1][t] = v.y;
            Xs[lk + 2][t] = v.z;
            Xs[lk + 3][t] = v.w;
        }
        // --- stage duplicated W chunk [BKk][128] ---
        #pragma unroll
        for (int pass = 0; pass < 4; ++pass) {
            int idx = pass * 256 + tid;
            int row = idx >> 5;
            int c4  = (idx & 31) * 4;
            float4 v = *reinterpret_cast<const float4*>(
                &g_wdup[(kc * BKk + row) * 128 + c4]);
            *reinterpret_cast<float4*>(&Ws[row][c4]) = v;
        }
        __syncthreads();

        #pragma unroll
        for (int kk = 0; kk < BKk; ++kk) {
            ulonglong2 xa = *reinterpret_cast<const ulonglong2*>(&Xs[kk][8 * ty]);
            ulonglong2 xb = *reinterpret_cast<const ulonglong2*>(&Xs[kk][8 * ty + 4]);
            ulonglong2 wa = *reinterpret_cast<const ulonglong2*>(&Ws[kk][8 * tx]);
            ulonglong2 wb = *reinterpret_cast<const ulonglong2*>(&Ws[kk][8 * tx + 4]);
            unsigned long long xv[4] = {xa.x, xa.y, xb.x, xb.y};
            unsigned long long wv[4] = {wa.x, wa.y, wb.x, wb.y};
            #pragma unroll
            for (int p = 0; p < 4; ++p)
                #pragma unroll
                for (int j = 0; j < 4; ++j)
                    fma2(acc[p][j], xv[p], wv[j]);
        }
        __syncthreads();
    }

    // --- spill logits to smem (aliases GEMM staging; safe after sync) ---
    #pragma unroll
    for (int p = 0; p < 4; ++p) {
        #pragma unroll
        for (int j = 0; j < 4; ++j) {
            float lo, hi;
            unpk(acc[p][j], lo, hi);
            L[8 * ty + 2 * p    ][4 * tx + j] = lo;
            L[8 * ty + 2 * p + 1][4 * tx + j] = hi;
        }
    }
    __syncthreads();

    // --- fused softmax + top-8, one warp per token (16 tokens per warp) ---
    const int lane = tid & 31, wrp = tid >> 5;
    const size_t tv_off = (size_t)N * 64;
    const size_t ix_off = tv_off + (size_t)N * 8;

    for (int i = 0; i < 16; ++i) {
        int t = wrp * 16 + i;
        float v0 = L[t][lane], v1 = L[t][lane + 32];
        float m = fmaxf(v0, v1);
        #pragma unroll
        for (int o = 16; o; o >>= 1) m = fmaxf(m, __shfl_xor_sync(0xffffffffu, m, o));
        float e0 = expf(v0 - m), e1 = expf(v1 - m);
        float s = e0 + e1;
        #pragma unroll
        for (int o = 16; o; o >>= 1) s += __shfl_xor_sync(0xffffffffu, s, o);
        float p0 = e0 / s, p1 = e1 / s;
        long gt = t0 + t;
        out[gt * 64 + lane]      = p0;
        out[gt * 64 + lane + 32] = p1;

        float a0 = p0, a1 = p1;
        #pragma unroll
        for (int r = 0; r < 8; ++r) {
            float bv; int bi;
            if (a0 >= a1) { bv = a0; bi = lane; }       // tie -> smaller index
            else          { bv = a1; bi = lane + 32; }
            #pragma unroll
            for (int o = 16; o; o >>= 1) {
                float ov = __shfl_xor_sync(0xffffffffu, bv, o);
                int   oi = __shfl_xor_sync(0xffffffffu, bi, o);
                if (ov > bv || (ov == bv && oi < bi)) { bv = ov; bi = oi; }
            }
            if (lane == 0) {
                out[tv_off + gt * 8 + r] = bv;
                out[ix_off + gt * 8 + r] = (float)bi;
            }
            if (bi == lane)           a0 = -1.0f;
            else if (bi == lane + 32) a1 = -1.0f;
        }
    }
}

extern "C" void kernel_launch(void* const* d_in, const int* in_sizes, int n_in,
                              void* d_out, int out_size) {
    const float* x = (const float*)d_in[0];
    const float* w = (const float*)d_in[1];
    float* out = (float*)d_out;
    int N = in_sizes[0] / Dd;                       // 32768 tokens

    dup_weight_kernel<<<(Dd * Ee + 255) / 256, 256>>>(w);
    router_kernel<<<N / TBt, NTHREADS>>>(x, out, N);
}

// round 5
// speedup vs baseline: 1.5474x; 1.5474x over previous
#include <cuda_runtime.h>
#include <cstdint>

// ============================================================================
// Router gate: x [32768, 2048] f32, w [64, 2048] f32.
// logits = x @ w^T ; probs = softmax ; top-8 vals + indices.
// Out: [probs N*64 | top_vals N*8 | indices(float) N*8]
//
// GEMM: mma m16n8k8 TF32, 2-way split (x=xh+xm, w=wh+wm):
//   xh*wh -> CHUNKED accumulator (k=64 chunks, re-based into a master fp32
//            register via RN FADD) — defeats tensor-core RZ-truncation bias
//            that capped R4 at ~5e-6 logit error.
//   xh*wm + xm*wh -> separate small-magnitude accumulator.
// ============================================================================

#define D 2048
#define TB 128            // tokens per CTA: warp tile m32 x n32, 8 warps
#define NSTEP 256         // k8 steps
#define NCHUNK 32         // staging+rebase chunks of 8 steps (k64)
#define STEP_BYTES 4096   // B frags per step: 8 tiles * 32 lanes * 16B
#define CHUNK_BYTES 32768
#define EPI_STRIDE 68
#define SMEM_SZ 65536

// weights split into tf32 h/m, HMMA B-fragment order:
// [step(256)][tile(8)][lane(32)] x uint4(bh0, bh1, bm0, bm1)
__device__ __align__(16) unsigned char g_bfrag[NSTEP * STEP_BYTES];

static __device__ __forceinline__ uint32_t smem_u32(const void* p) {
    uint32_t a;
    asm("{ .reg .u64 t; cvta.to.shared.u64 t, %1; cvt.u32.u64 %0, t; }"
        : "=r"(a) : "l"(p));
    return a;
}
static __device__ __forceinline__ void split2(float v, uint32_t& h, uint32_t& m) {
    asm("cvt.rna.tf32.f32 %0, %1;" : "=r"(h) : "f"(v));
    float r = v - __uint_as_float(h);
    asm("cvt.rna.tf32.f32 %0, %1;" : "=r"(m) : "f"(r));
}

// D = A*B + D
#define MMA(d, a0_, a1_, a2_, a3_, b0_, b1_) \
    asm volatile("mma.sync.aligned.m16n8k8.row.col.f32.tf32.tf32.f32 " \
        "{%0,%1,%2,%3}, {%4,%5,%6,%7}, {%8,%9}, {%0,%1,%2,%3};" \
        : "+f"((d)[0]), "+f"((d)[1]), "+f"((d)[2]), "+f"((d)[3]) \
        : "r"(a0_), "r"(a1_), "r"(a2_), "r"(a3_), "r"(b0_), "r"(b1_))
// D = A*B + 0   (chunk restart: C = zero regs, D written fresh)
#define MMA_ZC(d, a0_, a1_, a2_, a3_, b0_, b1_, z) \
    asm volatile("mma.sync.aligned.m16n8k8.row.col.f32.tf32.tf32.f32 " \
        "{%0,%1,%2,%3}, {%4,%5,%6,%7}, {%8,%9}, {%10,%11,%12,%13};" \
        : "=f"((d)[0]), "=f"((d)[1]), "=f"((d)[2]), "=f"((d)[3]) \
        : "r"(a0_), "r"(a1_), "r"(a2_), "r"(a3_), "r"(b0_), "r"(b1_), \
          "f"((z)[0]), "f"((z)[1]), "f"((z)[2]), "f"((z)[3]))

#define CP16(s, g) \
    asm volatile("cp.async.cg.shared.global [%0], [%1], 16;" :: "r"(s), "l"(g) : "memory")
#define CP_COMMIT() asm volatile("cp.async.commit_group;" ::: "memory")
#define CP_WAIT1()  asm volatile("cp.async.wait_group 1;" ::: "memory")
#define CP_WAIT0()  asm volatile("cp.async.wait_group 0;" ::: "memory")
#define LDS128(v, a) \
    asm volatile("ld.shared.v4.b32 {%0,%1,%2,%3}, [%4];" \
        : "=r"((v).x), "=r"((v).y), "=r"((v).z), "=r"((v).w) : "r"(a))

// ---------------- weight prep ----------------
__global__ void prep_bfrag(const float* __restrict__ w) {
    int i = blockIdx.x * blockDim.x + threadIdx.x;   // (step*8 + tile)*32 + lane
    if (i >= NSTEP * 8 * 32) return;
    int lane = i & 31;
    int tile = (i >> 5) & 7;
    int step = i >> 8;
    int e = tile * 8 + (lane >> 2);
    int tg = lane & 3;
    int k0 = step * 8;
    const float* wr = w + (size_t)e * D;
    uint32_t h0, m0, h1, m1;
    split2(wr[k0 + tg],     h0, m0);
    split2(wr[k0 + tg + 4], h1, m1);
    *reinterpret_cast<uint4*>(g_bfrag + step * STEP_BYTES + tile * 512 + lane * 16) =
        make_uint4(h0, h1, m0, m1);
}

// ---------------- main fused kernel ----------------
__global__ void __launch_bounds__(256, 1)
moe_gate(const float* __restrict__ x, float* __restrict__ out, int Ntok) {
    extern __shared__ __align__(16) float smemf[];
    const uint32_t sbase = smem_u32(smemf);
    const int tid = threadIdx.x;
    const int wid = tid >> 5;
    const int lane = tid & 31;
    const int g = lane >> 2;
    const int t4 = lane & 3;
    const int tg = wid >> 1;          // token group 0..3 (32 tokens each)
    const int eh = wid & 1;           // expert half 0..1 (32 experts)
    const size_t t0 = (size_t)blockIdx.x * TB;

    const float* px[4];
    px[0] = x + (t0 + tg * 32 + g) * D;
    px[1] = px[0] + 8 * D;
    px[2] = px[0] + 16 * D;
    px[3] = px[0] + 24 * D;

    // [mhalf*4 + jtile][4]
    float chx[8][4];    // hh chunk accumulator (rebased every k64)
    float ms[8][4];     // master (RN FADD sums of chunks)
    float cc[8][4];     // correction accumulator (hm + mh)
    float z4[4] = {0.f, 0.f, 0.f, 0.f};
    #pragma unroll
    for (int i = 0; i < 8; ++i)
        #pragma unroll
        for (int j = 0; j < 4; ++j) { ms[i][j] = 0.0f; cc[i][j] = 0.0f; }

    // prologue: stage chunk 0 (32KB)
    #pragma unroll
    for (int p = 0; p < 8; ++p) {
        int u = tid + p * 256;
        CP16(sbase + u * 16, g_bfrag + u * 16);
    }
    CP_COMMIT();

    float xa[8];
    #pragma unroll
    for (int r = 0; r < 4; ++r) {
        xa[2 * r]     = px[r][t4];
        xa[2 * r + 1] = px[r][t4 + 4];
    }

    for (int ch = 0; ch < NCHUNK; ++ch) {
        if (ch + 1 < NCHUNK) {
            const unsigned char* gsrc = g_bfrag + (size_t)(ch + 1) * CHUNK_BYTES;
            uint32_t sdst = sbase + ((ch + 1) & 1) * CHUNK_BYTES;
            #pragma unroll
            for (int p = 0; p < 8; ++p) {
                int u = tid + p * 256;
                CP16(sdst + u * 16, gsrc + u * 16);
            }
            CP_COMMIT();
            CP_WAIT1();
        } else {
            CP_WAIT0();
        }
        __syncthreads();

        const uint32_t stg = sbase + (ch & 1) * CHUNK_BYTES;
        #pragma unroll
        for (int s8 = 0; s8 < 8; ++s8) {
            const int step = ch * 8 + s8;
            float xn[8];
            if (step + 1 < NSTEP) {
                int kn = (step + 1) * 8 + t4;
                #pragma unroll
                for (int r = 0; r < 4; ++r) {
                    xn[2 * r]     = px[r][kn];
                    xn[2 * r + 1] = px[r][kn + 4];
                }
            }
            uint32_t Ah0[4], Am0[4], Ah1[4], Am1[4];
            split2(xa[0], Ah0[0], Am0[0]);
            split2(xa[2], Ah0[1], Am0[1]);
            split2(xa[1], Ah0[2], Am0[2]);
            split2(xa[3], Ah0[3], Am0[3]);
            split2(xa[4], Ah1[0], Am1[0]);
            split2(xa[6], Ah1[1], Am1[1]);
            split2(xa[5], Ah1[2], Am1[2]);
            split2(xa[7], Ah1[3], Am1[3]);

            const uint32_t bbase = stg + s8 * STEP_BYTES + eh * 2048 + lane * 16;
            #pragma unroll
            for (int j = 0; j < 4; ++j) {
                uint4 b; LDS128(b, bbase + j * 512);
                if (s8 == 0) {   // chunk restart: accumulate onto zero C
                    MMA_ZC(chx[j],     Ah0[0], Ah0[1], Ah0[2], Ah0[3], b.x, b.y, z4);
                    MMA_ZC(chx[4 + j], Ah1[0], Ah1[1], Ah1[2], Ah1[3], b.x, b.y, z4);
                } else {
                    MMA(chx[j],     Ah0[0], Ah0[1], Ah0[2], Ah0[3], b.x, b.y);
                    MMA(chx[4 + j], Ah1[0], Ah1[1], Ah1[2], Ah1[3], b.x, b.y);
                }
                MMA(cc[j],     Am0[0], Am0[1], Am0[2], Am0[3], b.x, b.y);
                MMA(cc[j],     Ah0[0], Ah0[1], Ah0[2], Ah0[3], b.z, b.w);
                MMA(cc[4 + j], Am1[0], Am1[1], Am1[2], Am1[3], b.x, b.y);
                MMA(cc[4 + j], Ah1[0], Ah1[1], Ah1[2], Ah1[3], b.z, b.w);
            }
            #pragma unroll
            for (int r = 0; r < 8; ++r) xa[r] = xn[r];
        }
        // rebase: master += chunk (RN fp32 adds, unbiased)
        #pragma unroll
        for (int i = 0; i < 8; ++i)
            #pragma unroll
            for (int j = 0; j < 4; ++j) ms[i][j] += chx[i][j];
        __syncthreads();
    }

    // -------- epilogue --------
    float* L = smemf;   // [128][EPI_STRIDE]
    #pragma unroll
    for (int j = 0; j < 4; ++j) {
        int n0 = eh * 32 + j * 8 + 2 * t4;
        int r0 = tg * 32 + g;
        *reinterpret_cast<float2*>(L + r0 * EPI_STRIDE + n0) =
            make_float2(ms[j][0] + cc[j][0], ms[j][1] + cc[j][1]);
        *reinterpret_cast<float2*>(L + (r0 + 8) * EPI_STRIDE + n0) =
            make_float2(ms[j][2] + cc[j][2], ms[j][3] + cc[j][3]);
        *reinterpret_cast<float2*>(L + (r0 + 16) * EPI_STRIDE + n0) =
            make_float2(ms[4 + j][0] + cc[4 + j][0], ms[4 + j][1] + cc[4 + j][1]);
        *reinterpret_cast<float2*>(L + (r0 + 24) * EPI_STRIDE + n0) =
            make_float2(ms[4 + j][2] + cc[4 + j][2], ms[4 + j][3] + cc[4 + j][3]);
    }
    __syncthreads();

    if (tid < TB) {
        float pv[64];
        const float* Lr = L + tid * EPI_STRIDE;
        #pragma unroll
        for (int c = 0; c < 16; ++c) {
            float4 v = *reinterpret_cast<const float4*>(Lr + 4 * c);
            pv[4 * c] = v.x; pv[4 * c + 1] = v.y;
            pv[4 * c + 2] = v.z; pv[4 * c + 3] = v.w;
        }
        float mx = pv[0];
        #pragma unroll
        for (int c = 1; c < 64; ++c) mx = fmaxf(mx, pv[c]);
        float s = 0.0f;
        #pragma unroll
        for (int c = 0; c < 64; ++c) { pv[c] = __expf(pv[c] - mx); s += pv[c]; }
        float inv = 1.0f / s;
        #pragma unroll
        for (int c = 0; c < 64; ++c) pv[c] *= inv;

        const size_t gt = t0 + tid;
        float* pr = out + gt * 64;
        #pragma unroll
        for (int c = 0; c < 16; ++c)
            *reinterpret_cast<float4*>(pr + 4 * c) =
                make_float4(pv[4 * c], pv[4 * c + 1], pv[4 * c + 2], pv[4 * c + 3]);

        float tv[8]; int ti[8];
        #pragma unroll
        for (int r = 0; r < 8; ++r) { tv[r] = -1.0f; ti[r] = 0; }
        #pragma unroll
        for (int j = 0; j < 64; ++j) {
            float v = pv[j];
            if (v > tv[7]) {
                tv[7] = v; ti[7] = j;
                #pragma unroll
                for (int q = 7; q > 0; --q) {
                    bool sw = tv[q] > tv[q - 1];
                    float fv = sw ? tv[q - 1] : tv[q];
                    int   fi = sw ? ti[q - 1] : ti[q];
                    tv[q - 1] = sw ? tv[q] : tv[q - 1];
                    ti[q - 1] = sw ? ti[q] : ti[q - 1];
                    tv[q] = fv; ti[q] = fi;
                }
            }
        }
        const size_t tvo = (size_t)Ntok * 64;
        const size_t ixo = tvo + (size_t)Ntok * 8;
        *reinterpret_cast<float4*>(out + tvo + gt * 8)     =
            make_float4(tv[0], tv[1], tv[2], tv[3]);
        *reinterpret_cast<float4*>(out + tvo + gt * 8 + 4) =
            make_float4(tv[4], tv[5], tv[6], tv[7]);
        *reinterpret_cast<float4*>(out + ixo + gt * 8)     =
            make_float4((float)ti[0], (float)ti[1], (float)ti[2], (float)ti[3]);
        *reinterpret_cast<float4*>(out + ixo + gt * 8 + 4) =
            make_float4((float)ti[4], (float)ti[5], (float)ti[6], (float)ti[7]);
    }
}

extern "C" void kernel_launch(void* const* d_in, const int* in_sizes, int n_in,
                              void* d_out, int out_size) {
    const float* x = (const float*)d_in[0];
    const float* w = (const float*)d_in[1];
    float* out = (float*)d_out;
    int Ntok = in_sizes[0] / D;

    cudaFuncSetAttribute(moe_gate, cudaFuncAttributeMaxDynamicSharedMemorySize, SMEM_SZ);
    prep_bfrag<<<(NSTEP * 8 * 32 + 255) / 256, 256>>>(w);
    moe_gate<<<Ntok / TB, 256, SMEM_SZ>>>(x, out, Ntok);
}

// round 6
// speedup vs baseline: 2.1949x; 1.4185x over previous
#include <cuda_runtime.h>
#include <cstdint>

// ============================================================================
// Router gate: x [32768, 2048] f32, w [64, 2048] f32.
// logits = x @ w^T ; probs = softmax ; top-8 vals + indices.
// Out: [probs N*64 | top_vals N*8 | indices(float) N*8]
//
// mma m16n8k8 TF32, 2-way split (x=xh+xm, w=wh+wm):
//   xh*wh -> chunk accumulator, rebased every k32 into master via RN FADD
//            (kills tensor-core RZ accumulation bias)
//   xh*wm + xm*wh -> separate small-magnitude accumulator
// R6: x staged via cp.async into swizzled smem (read once per CTA, conflict-
// free fragment LDS), warp tile m32n16, 16 warps -> 2x occupancy, regs ~100.
// ============================================================================

#define D 2048
#define TB 128            // tokens per CTA
#define NSTEP 256         // k8 steps
#define NCH 64            // k32 chunks (4 steps)
#define BSTEP 4096        // B frag bytes per step
#define BCHUNK 16384
#define XCHUNK 18432      // 128 rows * 36 floats * 4B (stride-36 swizzle)
#define EPI_STRIDE 68
#define SMEM_SZ (2 * BCHUNK + 2 * XCHUNK)   // 69632

// weights split into tf32 h/m, HMMA B-fragment order:
// [step(256)][tile(8)][lane(32)] x uint4(bh0, bh1, bm0, bm1)
__device__ __align__(16) unsigned char g_bfrag[NSTEP * BSTEP];

static __device__ __forceinline__ uint32_t smem_u32(const void* p) {
    uint32_t a;
    asm("{ .reg .u64 t; cvta.to.shared.u64 t, %1; cvt.u32.u64 %0, t; }"
        : "=r"(a) : "l"(p));
    return a;
}
static __device__ __forceinline__ void split2(float v, uint32_t& h, uint32_t& m) {
    asm("cvt.rna.tf32.f32 %0, %1;" : "=r"(h) : "f"(v));
    float r = v - __uint_as_float(h);
    asm("cvt.rna.tf32.f32 %0, %1;" : "=r"(m) : "f"(r));
}

#define MMA(d, a, b0_, b1_) \
    asm volatile("mma.sync.aligned.m16n8k8.row.col.f32.tf32.tf32.f32 " \
        "{%0,%1,%2,%3}, {%4,%5,%6,%7}, {%8,%9}, {%0,%1,%2,%3};" \
        : "+f"((d)[0]), "+f"((d)[1]), "+f"((d)[2]), "+f"((d)[3]) \
        : "r"((a)[0]), "r"((a)[1]), "r"((a)[2]), "r"((a)[3]), "r"(b0_), "r"(b1_))
// chunk restart: C = 0
#define MMA_ZC(d, a, b0_, b1_) \
    asm volatile("mma.sync.aligned.m16n8k8.row.col.f32.tf32.tf32.f32 " \
        "{%0,%1,%2,%3}, {%4,%5,%6,%7}, {%8,%9}, {%10,%10,%10,%10};" \
        : "=f"((d)[0]), "=f"((d)[1]), "=f"((d)[2]), "=f"((d)[3]) \
        : "r"((a)[0]), "r"((a)[1]), "r"((a)[2]), "r"((a)[3]), "r"(b0_), "r"(b1_), \
          "f"(0.0f))

#define CP16(s, g) \
    asm volatile("cp.async.cg.shared.global [%0], [%1], 16;" :: "r"(s), "l"(g) : "memory")
#define CP_COMMIT() asm volatile("cp.async.commit_group;" ::: "memory")
#define CP_WAIT1()  asm volatile("cp.async.wait_group 1;" ::: "memory")
#define CP_WAIT0()  asm volatile("cp.async.wait_group 0;" ::: "memory")
#define LDS128(v, a) \
    asm volatile("ld.shared.v4.b32 {%0,%1,%2,%3}, [%4];" \
        : "=r"((v).x), "=r"((v).y), "=r"((v).z), "=r"((v).w) : "r"(a))

// ---------------- weight prep ----------------
__global__ void prep_bfrag(const float* __restrict__ w) {
    int i = blockIdx.x * blockDim.x + threadIdx.x;   // (step*8 + tile)*32 + lane
    if (i >= NSTEP * 8 * 32) return;
    int lane = i & 31;
    int tile = (i >> 5) & 7;
    int step = i >> 8;
    int e = tile * 8 + (lane >> 2);
    int tq = lane & 3;
    int k0 = step * 8;
    const float* wr = w + (size_t)e * D;
    uint32_t h0, m0, h1, m1;
    split2(wr[k0 + tq],     h0, m0);
    split2(wr[k0 + tq + 4], h1, m1);
    *reinterpret_cast<uint4*>(g_bfrag + step * BSTEP + tile * 512 + lane * 16) =
        make_uint4(h0, h1, m0, m1);
}

// ---------------- main fused kernel ----------------
__global__ void __launch_bounds__(512, 1)
moe_gate(const float* __restrict__ x, float* __restrict__ out, int Ntok) {
    extern __shared__ __align__(16) float smemf[];
    const uint32_t sbase = smem_u32(smemf);
    const int tid = threadIdx.x;
    const int wid = tid >> 5;
    const int lane = tid & 31;
    const int g = lane >> 2;
    const int t4 = lane & 3;
    const int tg = wid >> 2;          // token group 0..3 (32 tokens)
    const int eq = wid & 3;           // expert quarter 0..3 (16 experts)
    const size_t t0 = (size_t)blockIdx.x * TB;
    const unsigned char* xg = reinterpret_cast<const unsigned char*>(x + t0 * D);

    float chx[4][4], ms[4][4], cc[4][4];   // [mhalf*2 + j][4]
    #pragma unroll
    for (int i = 0; i < 4; ++i)
        #pragma unroll
        for (int j = 0; j < 4; ++j) { ms[i][j] = 0.0f; cc[i][j] = 0.0f; }

    // staging addresses
    const int srow = tid >> 3, scol = tid & 7;           // x: 2 x 16B per thread
    const int srow2 = (tid + 512) >> 3, scol2 = (tid + 512) & 7;

    // prologue: stage chunk 0 (B 16KB + X 16KB)
    {
        CP16(sbase + tid * 16,         g_bfrag + tid * 16);
        CP16(sbase + (tid + 512) * 16, g_bfrag + (tid + 512) * 16);
        uint32_t xd = sbase + 2 * BCHUNK;
        CP16(xd + srow  * 144 + scol  * 16, xg + (size_t)srow  * (D * 4) + scol  * 16);
        CP16(xd + srow2 * 144 + scol2 * 16, xg + (size_t)srow2 * (D * 4) + scol2 * 16);
    }
    CP_COMMIT();

    const int xoff0 = (tg * 32 + g) * 36 + t4;   // + s4*8 per step, rows +288/p

    for (int ch = 0; ch < NCH; ++ch) {
        if (ch + 1 < NCH) {
            const unsigned char* bsrc = g_bfrag + (size_t)(ch + 1) * BCHUNK;
            uint32_t bd = sbase + ((ch + 1) & 1) * BCHUNK;
            CP16(bd + tid * 16,         bsrc + tid * 16);
            CP16(bd + (tid + 512) * 16, bsrc + (tid + 512) * 16);
            uint32_t xd = sbase + 2 * BCHUNK + ((ch + 1) & 1) * XCHUNK;
            size_t kb = (size_t)(ch + 1) * 128;  // 32 floats
            CP16(xd + srow  * 144 + scol  * 16, xg + (size_t)srow  * (D * 4) + kb + scol  * 16);
            CP16(xd + srow2 * 144 + scol2 * 16, xg + (size_t)srow2 * (D * 4) + kb + scol2 * 16);
            CP_COMMIT();
            CP_WAIT1();
        } else {
            CP_WAIT0();
        }
        __syncthreads();

        const uint32_t bstg = sbase + (ch & 1) * BCHUNK + eq * 1024 + lane * 16;
        const float* Xs = smemf + (2 * BCHUNK) / 4 + ((ch & 1) * XCHUNK) / 4;

        #pragma unroll
        for (int s4 = 0; s4 < 4; ++s4) {
            // conflict-free fragment gather: bank = (4*row + t4 + 8*s4)%32
            const float* xp = Xs + xoff0 + s4 * 8;
            float x0 = xp[0],       x1 = xp[4];         // row g
            float x2 = xp[288],     x3 = xp[292];       // row g+8
            float x4 = xp[576],     x5 = xp[580];       // row g+16
            float x6 = xp[864],     x7 = xp[868];       // row g+24

            uint32_t Ah0[4], Am0[4], Ah1[4], Am1[4];
            split2(x0, Ah0[0], Am0[0]);
            split2(x2, Ah0[1], Am0[1]);
            split2(x1, Ah0[2], Am0[2]);
            split2(x3, Ah0[3], Am0[3]);
            split2(x4, Ah1[0], Am1[0]);
            split2(x6, Ah1[1], Am1[1]);
            split2(x5, Ah1[2], Am1[2]);
            split2(x7, Ah1[3], Am1[3]);

            const uint32_t bb = bstg + s4 * BSTEP;
            #pragma unroll
            for (int j = 0; j < 2; ++j) {
                uint4 b; LDS128(b, bb + j * 512);
                if (s4 == 0) {          // chunk restart onto zero C
                    MMA_ZC(chx[j],     Ah0, b.x, b.y);
                    MMA_ZC(chx[2 + j], Ah1, b.x, b.y);
                } else {
                    MMA(chx[j],     Ah0, b.x, b.y);
                    MMA(chx[2 + j], Ah1, b.x, b.y);
                }
                MMA(cc[j],     Am0, b.x, b.y);
                MMA(cc[j],     Ah0, b.z, b.w);
                MMA(cc[2 + j], Am1, b.x, b.y);
                MMA(cc[2 + j], Ah1, b.z, b.w);
            }
        }
        // rebase: master += chunk (RN fp32, unbiased)
        #pragma unroll
        for (int i = 0; i < 4; ++i)
            #pragma unroll
            for (int j = 0; j < 4; ++j) ms[i][j] += chx[i][j];
        __syncthreads();
    }

    // -------- epilogue: logits -> smem (reuses staging), softmax + top-8 ----
    float* L = smemf;   // [128][EPI_STRIDE]
    #pragma unroll
    for (int j = 0; j < 2; ++j) {
        int n0 = eq * 16 + j * 8 + 2 * t4;
        int r0 = tg * 32 + g;
        *reinterpret_cast<float2*>(L + r0 * EPI_STRIDE + n0) =
            make_float2(ms[j][0] + cc[j][0], ms[j][1] + cc[j][1]);
        *reinterpret_cast<float2*>(L + (r0 + 8) * EPI_STRIDE + n0) =
            make_float2(ms[j][2] + cc[j][2], ms[j][3] + cc[j][3]);
        *reinterpret_cast<float2*>(L + (r0 + 16) * EPI_STRIDE + n0) =
            make_float2(ms[2 + j][0] + cc[2 + j][0], ms[2 + j][1] + cc[2 + j][1]);
        *reinterpret_cast<float2*>(L + (r0 + 24) * EPI_STRIDE + n0) =
            make_float2(ms[2 + j][2] + cc[2 + j][2], ms[2 + j][3] + cc[2 + j][3]);
    }
    __syncthreads();

    if (tid < TB) {
        float pv[64];
        const float* Lr = L + tid * EPI_STRIDE;
        #pragma unroll
        for (int c = 0; c < 16; ++c) {
            float4 v = *reinterpret_cast<const float4*>(Lr + 4 * c);
            pv[4 * c] = v.x; pv[4 * c + 1] = v.y;
            pv[4 * c + 2] = v.z; pv[4 * c + 3] = v.w;
        }
        float mx = pv[0];
        #pragma unroll
        for (int c = 1; c < 64; ++c) mx = fmaxf(mx, pv[c]);
        float s = 0.0f;
        #pragma unroll
        for (int c = 0; c < 64; ++c) { pv[c] = __expf(pv[c] - mx); s += pv[c]; }
        float inv = 1.0f / s;
        #pragma unroll
        for (int c = 0; c < 64; ++c) pv[c] *= inv;

        const size_t gt = t0 + tid;
        float* pr = out + gt * 64;
        #pragma unroll
        for (int c = 0; c < 16; ++c)
            *reinterpret_cast<float4*>(pr + 4 * c) =
                make_float4(pv[4 * c], pv[4 * c + 1], pv[4 * c + 2], pv[4 * c + 3]);

        // top-8 insertion; strict '>' keeps smaller index on ties (lax.top_k)
        float tv[8]; int ti[8];
        #pragma unroll
        for (int r = 0; r < 8; ++r) { tv[r] = -1.0f; ti[r] = 0; }
        #pragma unroll
        for (int j = 0; j < 64; ++j) {
            float v = pv[j];
            if (v > tv[7]) {
                tv[7] = v; ti[7] = j;
                #pragma unroll
                for (int q = 7; q > 0; --q) {
                    bool sw = tv[q] > tv[q - 1];
                    float fv = sw ? tv[q - 1] : tv[q];
                    int   fi = sw ? ti[q - 1] : ti[q];
                    tv[q - 1] = sw ? tv[q] : tv[q - 1];
                    ti[q - 1] = sw ? ti[q] : ti[q - 1];
                    tv[q] = fv; ti[q] = fi;
                }
            }
        }
        const size_t tvo = (size_t)Ntok * 64;
        const size_t ixo = tvo + (size_t)Ntok * 8;
        *reinterpret_cast<float4*>(out + tvo + gt * 8)     =
            make_float4(tv[0], tv[1], tv[2], tv[3]);
        *reinterpret_cast<float4*>(out + tvo + gt * 8 + 4) =
            make_float4(tv[4], tv[5], tv[6], tv[7]);
        *reinterpret_cast<float4*>(out + ixo + gt * 8)     =
            make_float4((float)ti[0], (float)ti[1], (float)ti[2], (float)ti[3]);
        *reinterpret_cast<float4*>(out + ixo + gt * 8 + 4) =
            make_float4((float)ti[4], (float)ti[5], (float)ti[6], (float)ti[7]);
    }
}

extern "C" void kernel_launch(void* const* d_in, const int* in_sizes, int n_in,
                              void* d_out, int out_size) {
    const float* x = (const float*)d_in[0];
    const float* w = (const float*)d_in[1];
    float* out = (float*)d_out;
    int Ntok = in_sizes[0] / D;     // 32768

    cudaFuncSetAttribute(moe_gate, cudaFuncAttributeMaxDynamicSharedMemorySize, SMEM_SZ);
    prep_bfrag<<<(NSTEP * 8 * 32 + 255) / 256, 256>>>(w);
    moe_gate<<<Ntok / TB, 512, SMEM_SZ>>>(x, out, Ntok);
}